// round 6
// baseline (speedup 1.0000x reference)
#include <cuda_runtime.h>
#include <cuda_bf16.h>
#include <cstdint>

#define NPATH 8192
#define LMAX 32
#define DIN 256
#define EDIM 128
#define HDIM 128
#define G4 512
#define GRP 1024
#define RTOT (NPATH*LMAX)
#define LN_EPS 1e-5f

typedef unsigned long long ull;

// ---------------- device scratch (static, no allocation) ----------------
__device__ float g_gi[(size_t)RTOT*G4]; // 512 MB: x @ Wih^T + bih + bhh (valid t only)
__device__ float g_WhhT[HDIM*G4];       // Whh^T   [k][j]  (128 x 512)
__device__ float g_WihT[HDIM*G4];       // Wih^T   [k][j]  (128 x 512)
__device__ float g_WinT[DIN*EDIM];      // W_in^T  [d][e]  (256 x 128)
__device__ float g_h[NPATH*HDIM];
__device__ float g_logits[NPATH];
__device__ float g_e[NPATH];
__device__ unsigned g_gmax[GRP];
__device__ float g_gsum[GRP];
__device__ float g_cnt[GRP];
__device__ float g_wsum[GRP*HDIM];

__device__ __forceinline__ float sigm(float x) { return 1.0f / (1.0f + expf(-x)); }

__device__ __forceinline__ unsigned enc_f(float f) {
    unsigned u = __float_as_uint(f);
    return (u & 0x80000000u) ? ~u : (u | 0x80000000u);
}
__device__ __forceinline__ float dec_f(unsigned k) {
    return (k & 0x80000000u) ? __uint_as_float(k ^ 0x80000000u) : __uint_as_float(~k);
}

// ---------------- packed f32x2 helpers ----------------
__device__ __forceinline__ ull fma2(ull a, ull b, ull c) {
    ull d;
    asm("fma.rn.f32x2 %0, %1, %2, %3;" : "=l"(d) : "l"(a), "l"(b), "l"(c));
    return d;
}
__device__ __forceinline__ ull add2(ull a, ull b) {
    ull d;
    asm("add.rn.f32x2 %0, %1, %2;" : "=l"(d) : "l"(a), "l"(b));
    return d;
}
__device__ __forceinline__ ull pack2(float x, float y) {
    ull d;
    asm("mov.b64 %0, {%1, %2};" : "=l"(d) : "f"(x), "f"(y));
    return d;
}
__device__ __forceinline__ float2 unpack2(ull v) {
    float2 r;
    asm("mov.b64 {%0, %1}, %2;" : "=f"(r.x), "=f"(r.y) : "l"(v));
    return r;
}

// ---------------- cp.async helpers ----------------
__device__ __forceinline__ uint32_t smem_u32(const void* p) {
    uint32_t a;
    asm("{ .reg .u64 t; cvta.to.shared.u64 t, %1; cvt.u32.u64 %0, t; }" : "=r"(a) : "l"(p));
    return a;
}
__device__ __forceinline__ void cpa16(uint32_t dst, const float* src) {
    asm volatile("cp.async.cg.shared.global [%0], [%1], 16;" :: "r"(dst), "l"(src));
}
#define CP_COMMIT asm volatile("cp.async.commit_group;" ::: "memory")
#define CP_WAIT1  asm volatile("cp.async.wait_group 1;" ::: "memory")
#define CP_WAIT0  asm volatile("cp.async.wait_group 0;" ::: "memory")

// ---------------- kernel 0: transpose weights once ----------------
__global__ void __launch_bounds__(256) k_prep(const float* __restrict__ Whh,
                                              const float* __restrict__ Wih,
                                              const float* __restrict__ W_in) {
    int idx = blockIdx.x * 256 + threadIdx.x;   // 65536 total
    {
        int j = idx >> 7, k = idx & 127;
        g_WhhT[k * G4 + j] = Whh[j * HDIM + k];
        g_WihT[k * G4 + j] = Wih[j * HDIM + k];
    }
    if (idx < DIN * EDIM) {
        int e = idx >> 8, d = idx & 255;
        g_WinT[d * EDIM + e] = W_in[e * DIN + d];
    }
}

// ---------------- kernel 1: fused projection+LN+tanh + input-gate GEMM ----------------
// 1 block = 128 rows (4 paths), 256 threads, 8x8 register tiles, cp.async ping-pong.
__global__ void __launch_bounds__(256, 1) k_fp(const float* __restrict__ inp,
                                               const float* __restrict__ gamma,
                                               const float* __restrict__ beta,
                                               const float* __restrict__ bih,
                                               const float* __restrict__ bhh,
                                               const int* __restrict__ lens) {
    extern __shared__ float sm[];
    float* Xs  = sm;                       // 128*132 = 16896
    float* As0 = sm + 16896;               // 128*36 = 4608
    float* As1 = As0 + 4608;
    float* Bs0 = As1 + 4608;               // 32*132 = 4224
    float* Bs1 = Bs0 + 4224;               // total 34560 floats = 138240 B
    __shared__ float sgam[128], sbet[128], sbias[512];
    __shared__ int len4[4];

    const int tid = threadIdx.x;
    const int tx = tid & 15, ty = tid >> 4;
    const int w = tid >> 5;
    const size_t r0 = (size_t)blockIdx.x * 128;
    const int pbase = blockIdx.x * 4;

    float* Asb[2] = {As0, As1};
    float* Bsb[2] = {Bs0, Bs1};
    uint32_t uAs[2] = {smem_u32(As0), smem_u32(As1)};
    uint32_t uBs[2] = {smem_u32(Bs0), smem_u32(Bs1)};

    // ---- prefetch phase1 stage 0 ----
    {
        const float* asrc = inp + r0 * DIN;
        const float* bsrc = g_WinT;
#pragma unroll
        for (int j = 0; j < 4; j++) {
            int c = tid + 256 * j;
            int row = c >> 3, kc = c & 7;
            cpa16(uAs[0] + row * 144 + kc * 16, asrc + (size_t)row * DIN + kc * 4);
        }
#pragma unroll
        for (int j = 0; j < 4; j++) {
            int c = tid + 256 * j;
            int kk = c >> 5, ec = c & 31;
            cpa16(uBs[0] + kk * 528 + ec * 16, bsrc + kk * EDIM + ec * 4);
        }
        CP_COMMIT;
    }

    if (tid < 128) { sgam[tid] = gamma[tid]; sbet[tid] = beta[tid]; }
    sbias[tid] = bih[tid] + bhh[tid];
    sbias[tid + 256] = bih[tid + 256] + bhh[tid + 256];
    if (tid < 4) len4[tid] = lens[pbase + tid];
    __syncthreads();
    const bool wactive = ((w & 1) * 16) < len4[w >> 1];

    // ---- phase 1: acc = inp_tile @ W_in^T ----
    ull acc[8][4];
#pragma unroll
    for (int i = 0; i < 8; i++)
#pragma unroll
        for (int j = 0; j < 4; j++) acc[i][j] = 0ull;

    for (int kt = 0; kt < 8; kt++) {
        if (kt < 7) {
            int pb = (kt + 1) & 1;
            const float* asrc = inp + r0 * DIN + (kt + 1) * 32;
            const float* bsrc = g_WinT + (size_t)(kt + 1) * 32 * EDIM;
#pragma unroll
            for (int j = 0; j < 4; j++) {
                int c = tid + 256 * j;
                int row = c >> 3, kc = c & 7;
                cpa16(uAs[pb] + row * 144 + kc * 16, asrc + (size_t)row * DIN + kc * 4);
            }
#pragma unroll
            for (int j = 0; j < 4; j++) {
                int c = tid + 256 * j;
                int kk = c >> 5, ec = c & 31;
                cpa16(uBs[pb] + kk * 528 + ec * 16, bsrc + kk * EDIM + ec * 4);
            }
            CP_COMMIT;
            CP_WAIT1;
        } else {
            CP_WAIT0;
        }
        __syncthreads();
        if (wactive) {
            const float* A = Asb[kt & 1];
            const float* B = Bsb[kt & 1];
#pragma unroll 2
            for (int kk = 0; kk < 32; kk++) {
                ulonglong2 b01 = *(const ulonglong2*)&B[kk * 132 + tx * 8];
                ulonglong2 b23 = *(const ulonglong2*)&B[kk * 132 + tx * 8 + 4];
#pragma unroll
                for (int i = 0; i < 8; i++) {
                    float a = A[(8 * ty + i) * 36 + kk];
                    ull a2 = pack2(a, a);
                    acc[i][0] = fma2(a2, b01.x, acc[i][0]);
                    acc[i][1] = fma2(a2, b01.y, acc[i][1]);
                    acc[i][2] = fma2(a2, b23.x, acc[i][2]);
                    acc[i][3] = fma2(a2, b23.y, acc[i][3]);
                }
            }
        }
        __syncthreads();
    }

    // ---- LN + tanh epilogue -> Xs ----
    if (wactive) {
        float gam[8], bet[8];
#pragma unroll
        for (int j = 0; j < 8; j++) { gam[j] = sgam[tx * 8 + j]; bet[j] = sbet[tx * 8 + j]; }
#pragma unroll
        for (int i = 0; i < 8; i++) {
            float v[8];
#pragma unroll
            for (int p = 0; p < 4; p++) {
                float2 u = unpack2(acc[i][p]);
                v[2 * p] = u.x; v[2 * p + 1] = u.y;
            }
            float s = 0.0f, q = 0.0f;
#pragma unroll
            for (int j = 0; j < 8; j++) { s += v[j]; q += v[j] * v[j]; }
#pragma unroll
            for (int m = 8; m >= 1; m >>= 1) {
                s += __shfl_xor_sync(0xffffffffu, s, m);
                q += __shfl_xor_sync(0xffffffffu, q, m);
            }
            float mu = s * (1.0f / 128.0f);
            float var = q * (1.0f / 128.0f) - mu * mu;
            float rs = rsqrtf(var + LN_EPS);
            int row = 8 * ty + i;
#pragma unroll
            for (int j = 0; j < 8; j++)
                Xs[row * 132 + tx * 8 + j] = tanhf((v[j] - mu) * rs * gam[j] + bet[j]);
        }
    }
    __syncthreads();

    // ---- phase 2: gi = Xs @ Wih^T + b (16 stages: j0 0..3 x kt 0..3) ----
    // prefetch stage 0
    {
        const float* bsrc = g_WihT;   // kt=0, j0=0
#pragma unroll
        for (int j = 0; j < 4; j++) {
            int c = tid + 256 * j;
            int kk = c >> 5, ec = c & 31;
            cpa16(uBs[0] + kk * 528 + ec * 16, bsrc + (size_t)kk * G4 + ec * 4);
        }
        CP_COMMIT;
    }

    for (int s = 0; s < 16; s++) {
        int j0 = s >> 2, kt = s & 3;
        if (kt == 0) {
#pragma unroll
            for (int i = 0; i < 8; i++)
#pragma unroll
                for (int j = 0; j < 4; j++) acc[i][j] = 0ull;
        }
        if (s < 15) {
            int s1 = s + 1;
            int pb = s1 & 1;
            const float* bsrc = g_WihT + (size_t)((s1 & 3) * 32) * G4 + (s1 >> 2) * 128;
#pragma unroll
            for (int j = 0; j < 4; j++) {
                int c = tid + 256 * j;
                int kk = c >> 5, ec = c & 31;
                cpa16(uBs[pb] + kk * 528 + ec * 16, bsrc + (size_t)kk * G4 + ec * 4);
            }
            CP_COMMIT;
            CP_WAIT1;
        } else {
            CP_WAIT0;
        }
        __syncthreads();
        if (wactive) {
            const float* B = Bsb[s & 1];
            const int kb = kt * 32;
#pragma unroll 2
            for (int kk = 0; kk < 32; kk++) {
                ulonglong2 b01 = *(const ulonglong2*)&B[kk * 132 + tx * 8];
                ulonglong2 b23 = *(const ulonglong2*)&B[kk * 132 + tx * 8 + 4];
#pragma unroll
                for (int i = 0; i < 8; i++) {
                    float a = Xs[(8 * ty + i) * 132 + kb + kk];
                    ull a2 = pack2(a, a);
                    acc[i][0] = fma2(a2, b01.x, acc[i][0]);
                    acc[i][1] = fma2(a2, b01.y, acc[i][1]);
                    acc[i][2] = fma2(a2, b23.x, acc[i][2]);
                    acc[i][3] = fma2(a2, b23.y, acc[i][3]);
                }
            }
            if (kt == 3) {
                ulonglong2 bp01 = *(const ulonglong2*)&sbias[j0 * 128 + tx * 8];
                ulonglong2 bp23 = *(const ulonglong2*)&sbias[j0 * 128 + tx * 8 + 4];
#pragma unroll
                for (int i = 0; i < 8; i++) {
                    int row = 8 * ty + i;
                    int t = row & 31, p = row >> 5;
                    if (t < len4[p]) {
                        float2 v0 = unpack2(add2(acc[i][0], bp01.x));
                        float2 v1 = unpack2(add2(acc[i][1], bp01.y));
                        float2 v2 = unpack2(add2(acc[i][2], bp23.x));
                        float2 v3 = unpack2(add2(acc[i][3], bp23.y));
                        size_t base = ((size_t)(pbase + p) * LMAX + t) * G4 + j0 * 128 + tx * 8;
                        *(float4*)&g_gi[base]     = make_float4(v0.x, v0.y, v1.x, v1.y);
                        *(float4*)&g_gi[base + 4] = make_float4(v2.x, v2.y, v3.x, v3.y);
                    }
                }
            }
        }
        __syncthreads();
    }
}

// ---------------- kernel 2: LSTM recurrence ----------------
// 64 paths/block, 512 threads: ty = tid>>6 owns 8 paths, tx = tid&63 owns 2 cols/gate.
// hs stored duplicated-transposed: hs[k][2n] = hs[k][2n+1] = h[n][k] -> A loads are f32x2 pairs.
__global__ void __launch_bounds__(512, 1) k_lstm(const int* __restrict__ lens) {
    extern __shared__ float sm[];
    float* hs  = sm;                 // 128 * 132 = 16896 floats
    float* Bs0 = sm + 16896;         // 32 * 520 = 16640
    float* Bs1 = Bs0 + 16640;        // total 50176 floats = 200704 B
    __shared__ int ln_s[64];
    __shared__ int blkmax_s;

    const int tid = threadIdx.x;
    const int tx = tid & 63, ty = tid >> 6;
    const int n0 = blockIdx.x * 64;

    float* Bsb[2] = {Bs0, Bs1};
    uint32_t uBs[2] = {smem_u32(Bs0), smem_u32(Bs1)};

    // prefetch kt=0
    {
#pragma unroll
        for (int j = 0; j < 8; j++) {
            int c = tid + 512 * j;
            int kk = c >> 7, ec = c & 127;
            cpa16(uBs[0] + kk * 2080 + ec * 16, g_WhhT + (size_t)kk * G4 + ec * 4);
        }
        CP_COMMIT;
    }

    // zero hs
#pragma unroll
    for (int s = 0; s < 33; s++) {
        int idx = tid + s * 512;
        if (idx < 16896) hs[idx] = 0.0f;
    }
    if (tid < 64) {
        int l = lens[n0 + tid];
        ln_s[tid] = l;
    }
    __syncthreads();
    if (tid == 0) {
        int m = 0;
        for (int i = 0; i < 64; i++) m = max(m, ln_s[i]);
        blkmax_s = m;
    }
    int myln[8];
    int wmax = 0;
#pragma unroll
    for (int i = 0; i < 8; i++) { myln[i] = ln_s[8 * ty + i]; wmax = max(wmax, myln[i]); }
    __syncthreads();
    const int blkmax = blkmax_s;

    float2 c[8];
#pragma unroll
    for (int i = 0; i < 8; i++) c[i] = make_float2(0.0f, 0.0f);

    for (int t = 0; t < blkmax; t++) {
        ull acc[8][4];
#pragma unroll
        for (int i = 0; i < 8; i++)
#pragma unroll
            for (int q = 0; q < 4; q++) acc[i][q] = 0ull;

        const bool active = (t < wmax);

        for (int kt = 0; kt < 4; kt++) {
            bool last = (t == blkmax - 1) && (kt == 3);
            if (!last) {
                int nk = (kt + 1) & 3;
                int pb = (kt + 1) & 1;
                const float* bsrc = g_WhhT + (size_t)(nk * 32) * G4;
#pragma unroll
                for (int j = 0; j < 8; j++) {
                    int cc = tid + 512 * j;
                    int kk = cc >> 7, ec = cc & 127;
                    cpa16(uBs[pb] + kk * 2080 + ec * 16, bsrc + (size_t)kk * G4 + ec * 4);
                }
                CP_COMMIT;
                CP_WAIT1;
            } else {
                CP_WAIT0;
            }
            __syncthreads();
            if (active) {
                const float* B = Bsb[kt & 1];
                const int kb = kt * 32;
#pragma unroll 2
                for (int kk = 0; kk < 32; kk++) {
                    const float* hrow = &hs[(kb + kk) * 132 + 16 * ty];
                    ulonglong2 a01 = *(const ulonglong2*)(hrow);
                    ulonglong2 a23 = *(const ulonglong2*)(hrow + 4);
                    ulonglong2 a45 = *(const ulonglong2*)(hrow + 8);
                    ulonglong2 a67 = *(const ulonglong2*)(hrow + 12);
                    ull A[8] = {a01.x, a01.y, a23.x, a23.y, a45.x, a45.y, a67.x, a67.y};
#pragma unroll
                    for (int q = 0; q < 4; q++) {
                        ull b = *(const ull*)&B[kk * 520 + q * 128 + 2 * tx];
#pragma unroll
                        for (int i = 0; i < 8; i++)
                            acc[i][q] = fma2(A[i], b, acc[i][q]);
                    }
                }
            }
            __syncthreads();
        }

        // cell update
        if (active) {
#pragma unroll
            for (int i = 0; i < 8; i++) {
                if (t < myln[i]) {
                    int n = 8 * ty + i;
                    size_t base = ((size_t)(n0 + n) * LMAX + t) * G4 + 2 * tx;
                    float2 gi = *(const float2*)&g_gi[base];
                    float2 gf = *(const float2*)&g_gi[base + 128];
                    float2 gg = *(const float2*)&g_gi[base + 256];
                    float2 go = *(const float2*)&g_gi[base + 384];
                    float2 ai = unpack2(acc[i][0]);
                    float2 af = unpack2(acc[i][1]);
                    float2 ag = unpack2(acc[i][2]);
                    float2 ao = unpack2(acc[i][3]);
                    float cx = sigm(gf.x + af.x) * c[i].x + sigm(gi.x + ai.x) * tanhf(gg.x + ag.x);
                    float cy = sigm(gf.y + af.y) * c[i].y + sigm(gi.y + ai.y) * tanhf(gg.y + ag.y);
                    c[i] = make_float2(cx, cy);
                    float h0 = sigm(go.x + ao.x) * tanhf(cx);
                    float h1 = sigm(go.y + ao.y) * tanhf(cy);
                    *(float2*)&hs[(2 * tx) * 132 + 2 * n]     = make_float2(h0, h0);
                    *(float2*)&hs[(2 * tx + 1) * 132 + 2 * n] = make_float2(h1, h1);
                }
            }
        }
        __syncthreads();
    }

    // store final h
#pragma unroll
    for (int s = 0; s < 16; s++) {
        int idx = tid + 512 * s;
        int k = idx & 127, n = idx >> 7;
        g_h[(size_t)(n0 + n) * HDIM + k] = hs[k * 132 + 2 * n];
    }
}

// ---------------- kernel 3a: init accumulators ----------------
__global__ void k_init() {
    int i = blockIdx.x * blockDim.x + threadIdx.x;
    if (i < GRP * HDIM) g_wsum[i] = 0.0f;
    if (i < GRP) {
        g_gsum[i] = 0.0f;
        g_cnt[i] = 0.0f;
        g_gmax[i] = 0u;
    }
}

// ---------------- kernel 3b: attention logits + segment max ----------------
__global__ void __launch_bounds__(256) k_logits(const float* __restrict__ ap,
                                                const int* __restrict__ seg) {
    int w = threadIdx.x >> 5, lane = threadIdx.x & 31;
    int n = blockIdx.x * 8 + w;
    float s = 0.0f;
#pragma unroll
    for (int q = 0; q < 4; q++) s += g_h[n * HDIM + lane + 32 * q] * ap[lane + 32 * q];
#pragma unroll
    for (int m = 16; m >= 1; m >>= 1) s += __shfl_xor_sync(0xffffffffu, s, m);
    if (lane == 0) {
        g_logits[n] = s;
        atomicMax(&g_gmax[seg[n]], enc_f(s));
    }
}

// ---------------- kernel 3c: exp + segment sum + count ----------------
__global__ void __launch_bounds__(256) k_expsum(const int* __restrict__ seg) {
    int n = blockIdx.x * 256 + threadIdx.x;
    int g = seg[n];
    float e = expf(g_logits[n] - dec_f(g_gmax[g]));
    g_e[n] = e;
    atomicAdd(&g_gsum[g], e);
    atomicAdd(&g_cnt[g], 1.0f);
}

// ---------------- kernel 3d: weighted hidden sum per group ----------------
__global__ void __launch_bounds__(256) k_wsum(const int* __restrict__ seg) {
    int w = threadIdx.x >> 5, lane = threadIdx.x & 31;
    int n = blockIdx.x * 8 + w;
    float e = g_e[n];
    int g = seg[n];
#pragma unroll
    for (int q = 0; q < 4; q++)
        atomicAdd(&g_wsum[g * HDIM + lane + 32 * q], e * g_h[n * HDIM + lane + 32 * q]);
}

// ---------------- kernel 4: head ----------------
__global__ void __launch_bounds__(256) k_head(const float* __restrict__ W_out,
                                              const float* __restrict__ W_cls,
                                              const float* __restrict__ ap,
                                              float* __restrict__ out,
                                              int out_size) {
    __shared__ float cs[16 * 128];
    __shared__ float cvs[16 * 128];
    const int tid = threadIdx.x;
    const int g0 = blockIdx.x * 16;
    const bool full = (out_size >= 2048 + GRP * HDIM + HDIM);

#pragma unroll
    for (int s = 0; s < 8; s++) {
        int idx = tid + s * 256;
        int gg = idx >> 7, k = idx & 127;
        int gi = g0 + gg;
        cs[gg * 128 + k] = g_wsum[gi * HDIM + k] / (g_gsum[gi] * g_cnt[gi]);
    }
    __syncthreads();

    int row = tid >> 4;
    int c0 = (tid & 15) * 8;
    float acc[8];
#pragma unroll
    for (int j = 0; j < 8; j++) acc[j] = 0.0f;
    for (int k = 0; k < 128; k++) {
        float a = cs[row * 128 + k];
#pragma unroll
        for (int j = 0; j < 8; j++) acc[j] += a * W_out[(c0 + j) * 128 + k];
    }
#pragma unroll
    for (int j = 0; j < 8; j++) {
        cvs[row * 128 + c0 + j] = acc[j];
        if (full) out[2048 + (g0 + row) * 128 + c0 + j] = acc[j];
    }
    __syncthreads();

    if (tid < 32) {
        int r = tid >> 1, c = tid & 1;
        float s = 0.0f;
        for (int k = 0; k < 128; k++) s += cvs[r * 128 + k] * W_cls[c * 128 + k];
        out[(g0 + r) * 2 + c] = s;
    }
    if (full && blockIdx.x == 0 && tid < 128) out[2048 + GRP * HDIM + tid] = ap[tid];
}

// ---------------- launch ----------------
extern "C" void kernel_launch(void* const* d_in, const int* in_sizes, int n_in,
                              void* d_out, int out_size) {
    const float* inputs = (const float*)d_in[0];
    const int* lens     = (const int*)d_in[1];
    const int* seg      = (const int*)d_in[2];
    const float* W_in   = (const float*)d_in[3];
    const float* gamma  = (const float*)d_in[4];
    const float* beta   = (const float*)d_in[5];
    const float* Wih    = (const float*)d_in[6];
    const float* Whh    = (const float*)d_in[7];
    const float* bih    = (const float*)d_in[8];
    const float* bhh    = (const float*)d_in[9];
    const float* ap     = (const float*)d_in[10];
    const float* W_out  = (const float*)d_in[11];
    const float* W_cls  = (const float*)d_in[12];
    float* out = (float*)d_out;

    const int fp_smem   = 34560 * 4;   // 138240 B
    const int lstm_smem = 50176 * 4;   // 200704 B
    cudaFuncSetAttribute(k_fp, cudaFuncAttributeMaxDynamicSharedMemorySize, fp_smem);
    cudaFuncSetAttribute(k_lstm, cudaFuncAttributeMaxDynamicSharedMemorySize, lstm_smem);

    k_prep<<<256, 256>>>(Whh, Wih, W_in);
    k_fp<<<RTOT / 128, 256, fp_smem>>>(inputs, gamma, beta, bih, bhh, lens);
    k_lstm<<<NPATH / 64, 512, lstm_smem>>>(lens);
    k_init<<<(GRP * HDIM + 255) / 256, 256>>>();
    k_logits<<<NPATH / 8, 256>>>(ap, seg);
    k_expsum<<<NPATH / 256, 256>>>(seg);
    k_wsum<<<NPATH / 8, 256>>>(seg);
    k_head<<<GRP / 16, 256>>>(W_out, W_cls, ap, out, out_size);
}

// round 7
// speedup vs baseline: 1.0972x; 1.0972x over previous
#include <cuda_runtime.h>
#include <cuda_bf16.h>
#include <cstdint>

#define NPATH 8192
#define LMAX 32
#define DIN 256
#define EDIM 128
#define HDIM 128
#define G4 512
#define GRP 1024
#define RTOT (NPATH*LMAX)
#define LN_EPS 1e-5f

typedef unsigned long long ull;

// ---------------- device scratch (static, no allocation) ----------------
__device__ float g_gi[(size_t)RTOT*G4]; // 512 MB: x @ Wih^T + bih + bhh (valid t only)
__device__ float g_WhhT[HDIM*G4];       // Whh^T [k][j]
__device__ float g_h[NPATH*HDIM];
__device__ float g_logits[NPATH];
__device__ float g_e[NPATH];
__device__ unsigned g_gmax[GRP];
__device__ float g_gsum[GRP];
__device__ float g_cnt[GRP];
__device__ float g_wsum[GRP*HDIM];
__device__ int g_lcnt[40];
__device__ int g_lstart[40];
__device__ int g_perm[NPATH];

__device__ __forceinline__ float sigm(float x) { return 1.0f / (1.0f + expf(-x)); }

__device__ __forceinline__ unsigned enc_f(float f) {
    unsigned u = __float_as_uint(f);
    return (u & 0x80000000u) ? ~u : (u | 0x80000000u);
}
__device__ __forceinline__ float dec_f(unsigned k) {
    return (k & 0x80000000u) ? __uint_as_float(k ^ 0x80000000u) : __uint_as_float(~k);
}

// ---------------- packed f32x2 helpers ----------------
__device__ __forceinline__ ull fma2(ull a, ull b, ull c) {
    ull d;
    asm("fma.rn.f32x2 %0, %1, %2, %3;" : "=l"(d) : "l"(a), "l"(b), "l"(c));
    return d;
}
__device__ __forceinline__ ull pack2(float x, float y) {
    ull d;
    asm("mov.b64 %0, {%1, %2};" : "=l"(d) : "f"(x), "f"(y));
    return d;
}
__device__ __forceinline__ float2 unpack2(ull v) {
    float2 r;
    asm("mov.b64 {%0, %1}, %2;" : "=f"(r.x), "=f"(r.y) : "l"(v));
    return r;
}

// ---------------- sort kernels (counting sort by length, descending) ----------------
__global__ void k_hist(const int* __restrict__ lens) {
    int n = blockIdx.x * 256 + threadIdx.x;
    if (n < NPATH) atomicAdd(&g_lcnt[lens[n]], 1);
}
__global__ void k_scan() {
    if (threadIdx.x == 0 && blockIdx.x == 0) {
        int run = 0;
        for (int l = LMAX; l >= 1; l--) { g_lstart[l] = run; run += g_lcnt[l]; }
    }
}
__global__ void k_scatter(const int* __restrict__ lens) {
    int n = blockIdx.x * 256 + threadIdx.x;
    if (n < NPATH) {
        int pos = atomicAdd(&g_lstart[lens[n]], 1);
        g_perm[pos] = n;
    }
}

// ---------------- kernel 0: transpose Whh once ----------------
__global__ void __launch_bounds__(256) k_tw(const float* __restrict__ Whh) {
    int idx = blockIdx.x * 256 + threadIdx.x;   // 65536 total
    int j = idx >> 7, k = idx & 127;
    g_WhhT[k * G4 + j] = Whh[j * HDIM + k];
}

// ---------------- kernel 1: fused projection+LN+tanh + input-gate GEMM ----------------
// block = 64 rows = 2 paths. Phase1 uses duplicated-transposed A (no packs).
__global__ void __launch_bounds__(256, 3) k_fp(const float* __restrict__ inp,
                                               const float* __restrict__ W_in,
                                               const float* __restrict__ gamma,
                                               const float* __restrict__ beta,
                                               const float* __restrict__ Wih,
                                               const float* __restrict__ bih,
                                               const float* __restrict__ bhh,
                                               const int* __restrict__ lens) {
    extern __shared__ float sm[];
    float* Xs = sm;                  // 64*132 = 8448
    float* Ad = sm + 8448;           // 32 kk * 132 (dup pairs, 128 used) = 4224
    float* Bs = Ad + 4224;           // 32*132 = 4224  -> total 16896 fl = 67584 B
    __shared__ int len2[2];

    const int tid = threadIdx.x;
    const int tx = tid & 15, ty = tid >> 4;
    const int w = tid >> 5;
    const int r0 = blockIdx.x * 64;

    if (tid < 2) len2[tid] = lens[blockIdx.x * 2 + tid];
    __syncthreads();
    const bool wactive = ((8 * w) & 31) < len2[w >> 2];

    // ---- phase 1: x = tanh(LN(inp @ W_in^T)) ----
    ull acc[4][4];
#pragma unroll
    for (int i = 0; i < 4; i++)
#pragma unroll
        for (int j = 0; j < 4; j++) acc[i][j] = 0ull;

    for (int kt = 0; kt < 8; kt++) {
        __syncthreads();
        const int kb = kt * 32;
#pragma unroll
        for (int s = 0; s < 8; s++) {
            int idx = tid + s * 256;
            int kk = idx & 31, r = idx >> 5;
            int t = r & 31, p = r >> 5;
            float v = (t < len2[p]) ? inp[(size_t)(r0 + r) * DIN + kb + kk] : 0.0f;
            *(float2*)&Ad[kk * 132 + 2 * r] = make_float2(v, v);
        }
#pragma unroll
        for (int s = 0; s < 16; s++) {
            int idx = tid + s * 256;
            int kk = idx & 31, e = idx >> 5;
            Bs[kk * 132 + e] = W_in[e * DIN + kb + kk];
        }
        __syncthreads();
        if (wactive) {
#pragma unroll 8
            for (int kk = 0; kk < 32; kk++) {
                ulonglong2 a01 = *(const ulonglong2*)&Ad[kk * 132 + 8 * ty];
                ulonglong2 a23 = *(const ulonglong2*)&Ad[kk * 132 + 8 * ty + 4];
                ull A2[4] = {a01.x, a01.y, a23.x, a23.y};
                ulonglong2 b01 = *(const ulonglong2*)&Bs[kk * 132 + tx * 8];
                ulonglong2 b23 = *(const ulonglong2*)&Bs[kk * 132 + tx * 8 + 4];
#pragma unroll
                for (int i = 0; i < 4; i++) {
                    acc[i][0] = fma2(A2[i], b01.x, acc[i][0]);
                    acc[i][1] = fma2(A2[i], b01.y, acc[i][1]);
                    acc[i][2] = fma2(A2[i], b23.x, acc[i][2]);
                    acc[i][3] = fma2(A2[i], b23.y, acc[i][3]);
                }
            }
        }
    }

    if (wactive) {
        float gam[8], bet[8];
#pragma unroll
        for (int j = 0; j < 8; j++) { gam[j] = gamma[tx * 8 + j]; bet[j] = beta[tx * 8 + j]; }
#pragma unroll
        for (int i = 0; i < 4; i++) {
            float v[8];
#pragma unroll
            for (int p = 0; p < 4; p++) {
                float2 u = unpack2(acc[i][p]);
                v[2 * p] = u.x; v[2 * p + 1] = u.y;
            }
            float s = 0.0f, q = 0.0f;
#pragma unroll
            for (int j = 0; j < 8; j++) { s += v[j]; q += v[j] * v[j]; }
#pragma unroll
            for (int m = 8; m >= 1; m >>= 1) {
                s += __shfl_xor_sync(0xffffffffu, s, m);
                q += __shfl_xor_sync(0xffffffffu, q, m);
            }
            float mu = s * (1.0f / 128.0f);
            float var = q * (1.0f / 128.0f) - mu * mu;
            float rs = rsqrtf(var + LN_EPS);
            int r = ty * 4 + i;
            float o[8];
#pragma unroll
            for (int j = 0; j < 8; j++) o[j] = tanhf((v[j] - mu) * rs * gam[j] + bet[j]);
            float4* dst = (float4*)&Xs[r * 132 + tx * 8];
            dst[0] = make_float4(o[0], o[1], o[2], o[3]);
            dst[1] = make_float4(o[4], o[5], o[6], o[7]);
        }
    }

    // ---- phase 2: gi = Xs @ Wih^T + b ----
    for (int j0t = 0; j0t < 4; j0t++) {
        const int j0 = j0t * 128;
        ull acc2[4][4];
#pragma unroll
        for (int i = 0; i < 4; i++)
#pragma unroll
            for (int j = 0; j < 4; j++) acc2[i][j] = 0ull;

        for (int kt = 0; kt < 4; kt++) {
            __syncthreads();
            const int kb = kt * 32;
#pragma unroll
            for (int s = 0; s < 16; s++) {
                int idx = tid + s * 256;
                int kk = idx & 31, j = idx >> 5;
                Bs[kk * 132 + j] = Wih[(j0 + j) * HDIM + kb + kk];
            }
            __syncthreads();
            if (wactive) {
#pragma unroll 8
                for (int kk = 0; kk < 32; kk++) {
                    ull a2[4];
#pragma unroll
                    for (int i = 0; i < 4; i++) {
                        float a = Xs[(ty * 4 + i) * 132 + kb + kk];
                        a2[i] = pack2(a, a);
                    }
                    ulonglong2 b01 = *(const ulonglong2*)&Bs[kk * 132 + tx * 8];
                    ulonglong2 b23 = *(const ulonglong2*)&Bs[kk * 132 + tx * 8 + 4];
#pragma unroll
                    for (int i = 0; i < 4; i++) {
                        acc2[i][0] = fma2(a2[i], b01.x, acc2[i][0]);
                        acc2[i][1] = fma2(a2[i], b01.y, acc2[i][1]);
                        acc2[i][2] = fma2(a2[i], b23.x, acc2[i][2]);
                        acc2[i][3] = fma2(a2[i], b23.y, acc2[i][3]);
                    }
                }
            }
        }
        if (wactive) {
            float bs[8];
#pragma unroll
            for (int j = 0; j < 8; j++) {
                int jj = j0 + tx * 8 + j;
                bs[j] = bih[jj] + bhh[jj];
            }
#pragma unroll
            for (int i = 0; i < 4; i++) {
                int r = ty * 4 + i;
                int t = r & 31, p = r >> 5;
                if (t < len2[p]) {
                    float v[8];
#pragma unroll
                    for (int pp = 0; pp < 4; pp++) {
                        float2 u = unpack2(acc2[i][pp]);
                        v[2 * pp] = u.x; v[2 * pp + 1] = u.y;
                    }
                    size_t base = ((size_t)(blockIdx.x * 2 + p) * LMAX + t) * G4 + j0 + tx * 8;
                    float4* dst = (float4*)&g_gi[base];
                    dst[0] = make_float4(v[0] + bs[0], v[1] + bs[1], v[2] + bs[2], v[3] + bs[3]);
                    dst[1] = make_float4(v[4] + bs[4], v[5] + bs[5], v[6] + bs[6], v[7] + bs[7]);
                }
            }
        }
    }
}

// ---------------- kernel 2: LSTM recurrence (sorted, balanced, dup-h) ----------------
// 32 sorted paths per block; group index pairs long+short groups on one SM.
// hs duplicated-transposed: hs[k][2n]=(h,h) -> A loads are broadcast LDS.128 pairs.
__global__ void __launch_bounds__(256, 2) k_lstm(const int* __restrict__ lens) {
    extern __shared__ float sm[];
    float* hs = sm;                 // 128 * 68 = 8704 floats (dup-transposed)
    float* Bs = sm + 8704;          // 32 * 520 = 16640 -> total 25344 fl = 101376 B
    __shared__ int ln_s[32];
    __shared__ int sp[32];
    __shared__ int maxlen_s;

    const int tid = threadIdx.x;
    const int tx = tid & 31, ty = tid >> 5;
    const int bid = blockIdx.x;
    const int gidx = (bid < 148) ? bid : (403 - bid);
    const int n0 = gidx * 32;

#pragma unroll
    for (int s = 0; s < 34; s++) {
        int idx = tid + s * 256;
        if (idx < 8704) hs[idx] = 0.0f;
    }
    if (tid < 32) {
        int pid = g_perm[n0 + tid];
        sp[tid] = pid;
        int l = lens[pid];
        ln_s[tid] = l;
#pragma unroll
        for (int m = 16; m >= 1; m >>= 1) l = max(l, __shfl_xor_sync(0xffffffffu, l, m));
        if (tid == 0) maxlen_s = l;
    }
    __syncthreads();

    int myln[4];
    int pid4[4];
    int mymax = 0;
#pragma unroll
    for (int i = 0; i < 4; i++) {
        myln[i] = ln_s[4 * ty + i];
        pid4[i] = sp[4 * ty + i];
        mymax = max(mymax, myln[i]);
    }
    const int blkmax = maxlen_s;

    float c[4][4];
#pragma unroll
    for (int i = 0; i < 4; i++)
#pragma unroll
        for (int j = 0; j < 4; j++) c[i][j] = 0.0f;

    for (int t = 0; t < blkmax; t++) {
        ull acc[4][4][2];
#pragma unroll
        for (int i = 0; i < 4; i++)
#pragma unroll
            for (int q = 0; q < 4; q++) { acc[i][q][0] = 0ull; acc[i][q][1] = 0ull; }

        const bool active = (t < mymax);

        for (int kt = 0; kt < 4; kt++) {
            __syncthreads();
#pragma unroll
            for (int s = 0; s < 16; s++) {
                int f4 = tid + s * 256;
                int kk = f4 >> 7;
                int col = (f4 & 127) * 4;
                *(float4*)&Bs[kk * 520 + col] =
                    *(const float4*)&g_WhhT[(kt * 32 + kk) * G4 + col];
            }
            __syncthreads();
            if (active) {
                const int kb = kt * 32;
#pragma unroll 8
                for (int kk = 0; kk < 32; kk++) {
                    ulonglong2 a01 = *(const ulonglong2*)&hs[(kb + kk) * 68 + 8 * ty];
                    ulonglong2 a23 = *(const ulonglong2*)&hs[(kb + kk) * 68 + 8 * ty + 4];
                    ull A2[4] = {a01.x, a01.y, a23.x, a23.y};
#pragma unroll
                    for (int q = 0; q < 4; q++) {
                        ulonglong2 b = *(const ulonglong2*)&Bs[kk * 520 + q * 128 + tx * 4];
#pragma unroll
                        for (int i = 0; i < 4; i++) {
                            acc[i][q][0] = fma2(A2[i], b.x, acc[i][q][0]);
                            acc[i][q][1] = fma2(A2[i], b.y, acc[i][q][1]);
                        }
                    }
                }
            }
        }

        if (active) {
#pragma unroll
            for (int i = 0; i < 4; i++) {
                if (t < myln[i]) {
                    int n = 4 * ty + i;
                    size_t base = ((size_t)pid4[i] * LMAX + t) * G4 + tx * 4;
                    float4 gi = *(const float4*)&g_gi[base];
                    float4 gf = *(const float4*)&g_gi[base + 128];
                    float4 gg = *(const float4*)&g_gi[base + 256];
                    float4 go = *(const float4*)&g_gi[base + 384];
                    float2 i0 = unpack2(acc[i][0][0]), i1 = unpack2(acc[i][0][1]);
                    float2 f0 = unpack2(acc[i][1][0]), f1 = unpack2(acc[i][1][1]);
                    float2 g0 = unpack2(acc[i][2][0]), g1 = unpack2(acc[i][2][1]);
                    float2 o0 = unpack2(acc[i][3][0]), o1 = unpack2(acc[i][3][1]);
                    float xi[4] = {gi.x + i0.x, gi.y + i0.y, gi.z + i1.x, gi.w + i1.y};
                    float xf[4] = {gf.x + f0.x, gf.y + f0.y, gf.z + f1.x, gf.w + f1.y};
                    float xg[4] = {gg.x + g0.x, gg.y + g0.y, gg.z + g1.x, gg.w + g1.y};
                    float xo[4] = {go.x + o0.x, go.y + o0.y, go.z + o1.x, go.w + o1.y};
#pragma unroll
                    for (int j = 0; j < 4; j++) {
                        float cn = sigm(xf[j]) * c[i][j] + sigm(xi[j]) * tanhf(xg[j]);
                        c[i][j] = cn;
                        float h = sigm(xo[j]) * tanhf(cn);
                        *(float2*)&hs[(tx * 4 + j) * 68 + 2 * n] = make_float2(h, h);
                    }
                }
            }
        }
        __syncthreads();
    }

#pragma unroll
    for (int s = 0; s < 16; s++) {
        int idx = tid + s * 256;
        int n = idx >> 7, k = idx & 127;
        g_h[(size_t)sp[n] * HDIM + k] = hs[k * 68 + 2 * n];
    }
}

// ---------------- kernel 3a: init accumulators (+ sort bins) ----------------
__global__ void k_init() {
    int i = blockIdx.x * blockDim.x + threadIdx.x;
    if (i < GRP * HDIM) g_wsum[i] = 0.0f;
    if (i < GRP) {
        g_gsum[i] = 0.0f;
        g_cnt[i] = 0.0f;
        g_gmax[i] = 0u;
    }
    if (i < 40) g_lcnt[i] = 0;
}

// ---------------- kernel 3b: attention logits + segment max ----------------
__global__ void __launch_bounds__(256) k_logits(const float* __restrict__ ap,
                                                const int* __restrict__ seg) {
    int w = threadIdx.x >> 5, lane = threadIdx.x & 31;
    int n = blockIdx.x * 8 + w;
    float s = 0.0f;
#pragma unroll
    for (int q = 0; q < 4; q++) s += g_h[n * HDIM + lane + 32 * q] * ap[lane + 32 * q];
#pragma unroll
    for (int m = 16; m >= 1; m >>= 1) s += __shfl_xor_sync(0xffffffffu, s, m);
    if (lane == 0) {
        g_logits[n] = s;
        atomicMax(&g_gmax[seg[n]], enc_f(s));
    }
}

// ---------------- kernel 3c: exp + segment sum + count ----------------
__global__ void __launch_bounds__(256) k_expsum(const int* __restrict__ seg) {
    int n = blockIdx.x * 256 + threadIdx.x;
    int g = seg[n];
    float e = expf(g_logits[n] - dec_f(g_gmax[g]));
    g_e[n] = e;
    atomicAdd(&g_gsum[g], e);
    atomicAdd(&g_cnt[g], 1.0f);
}

// ---------------- kernel 3d: weighted hidden sum per group ----------------
__global__ void __launch_bounds__(256) k_wsum(const int* __restrict__ seg) {
    int w = threadIdx.x >> 5, lane = threadIdx.x & 31;
    int n = blockIdx.x * 8 + w;
    float e = g_e[n];
    int g = seg[n];
#pragma unroll
    for (int q = 0; q < 4; q++)
        atomicAdd(&g_wsum[g * HDIM + lane + 32 * q], e * g_h[n * HDIM + lane + 32 * q]);
}

// ---------------- kernel 4: head ----------------
__global__ void __launch_bounds__(256) k_head(const float* __restrict__ W_out,
                                              const float* __restrict__ W_cls,
                                              const float* __restrict__ ap,
                                              float* __restrict__ out,
                                              int out_size) {
    __shared__ float cs[16 * 128];
    __shared__ float cvs[16 * 128];
    const int tid = threadIdx.x;
    const int g0 = blockIdx.x * 16;
    const bool full = (out_size >= 2048 + GRP * HDIM + HDIM);

#pragma unroll
    for (int s = 0; s < 8; s++) {
        int idx = tid + s * 256;
        int gg = idx >> 7, k = idx & 127;
        int gi = g0 + gg;
        cs[gg * 128 + k] = g_wsum[gi * HDIM + k] / (g_gsum[gi] * g_cnt[gi]);
    }
    __syncthreads();

    int row = tid >> 4;
    int c0 = (tid & 15) * 8;
    float acc[8];
#pragma unroll
    for (int j = 0; j < 8; j++) acc[j] = 0.0f;
    for (int k = 0; k < 128; k++) {
        float a = cs[row * 128 + k];
#pragma unroll
        for (int j = 0; j < 8; j++) acc[j] += a * W_out[(c0 + j) * 128 + k];
    }
#pragma unroll
    for (int j = 0; j < 8; j++) {
        cvs[row * 128 + c0 + j] = acc[j];
        if (full) out[2048 + (g0 + row) * 128 + c0 + j] = acc[j];
    }
    __syncthreads();

    if (tid < 32) {
        int r = tid >> 1, c = tid & 1;
        float s = 0.0f;
        for (int k = 0; k < 128; k++) s += cvs[r * 128 + k] * W_cls[c * 128 + k];
        out[(g0 + r) * 2 + c] = s;
    }
    if (full && blockIdx.x == 0 && tid < 128) out[2048 + GRP * HDIM + tid] = ap[tid];
}

// ---------------- launch ----------------
extern "C" void kernel_launch(void* const* d_in, const int* in_sizes, int n_in,
                              void* d_out, int out_size) {
    const float* inputs = (const float*)d_in[0];
    const int* lens     = (const int*)d_in[1];
    const int* seg      = (const int*)d_in[2];
    const float* W_in   = (const float*)d_in[3];
    const float* gamma  = (const float*)d_in[4];
    const float* beta   = (const float*)d_in[5];
    const float* Wih    = (const float*)d_in[6];
    const float* Whh    = (const float*)d_in[7];
    const float* bih    = (const float*)d_in[8];
    const float* bhh    = (const float*)d_in[9];
    const float* ap     = (const float*)d_in[10];
    const float* W_out  = (const float*)d_in[11];
    const float* W_cls  = (const float*)d_in[12];
    float* out = (float*)d_out;

    const int fp_smem   = 16896 * 4;   // 67584 B
    const int lstm_smem = 25344 * 4;   // 101376 B
    cudaFuncSetAttribute(k_fp, cudaFuncAttributeMaxDynamicSharedMemorySize, fp_smem);
    cudaFuncSetAttribute(k_lstm, cudaFuncAttributeMaxDynamicSharedMemorySize, lstm_smem);

    k_init<<<(GRP * HDIM + 255) / 256, 256>>>();
    k_hist<<<NPATH / 256, 256>>>(lens);
    k_scan<<<1, 32>>>();
    k_scatter<<<NPATH / 256, 256>>>(lens);
    k_tw<<<256, 256>>>(Whh);
    k_fp<<<RTOT / 64, 256, fp_smem>>>(inputs, W_in, gamma, beta, Wih, bih, bhh, lens);
    k_lstm<<<NPATH / 32, 256, lstm_smem>>>(lens);
    k_logits<<<NPATH / 8, 256>>>(ap, seg);
    k_expsum<<<NPATH / 256, 256>>>(seg);
    k_wsum<<<NPATH / 8, 256>>>(seg);
    k_head<<<GRP / 16, 256>>>(W_out, W_cls, ap, out, out_size);
}

// round 8
// speedup vs baseline: 1.2829x; 1.1693x over previous
#include <cuda_runtime.h>
#include <cuda_bf16.h>
#include <cstdint>

#define NPATH 8192
#define LMAX 32
#define DIN 256
#define EDIM 128
#define HDIM 128
#define G4 512
#define GRP 1024
#define RTOT (NPATH*LMAX)
#define LN_EPS 1e-5f

typedef unsigned long long ull;

// ---------------- device scratch (static, no allocation) ----------------
__device__ float g_gi[(size_t)RTOT*G4]; // 512 MB: x @ Wih^T + bih + bhh (valid t only)
__device__ float g_WhhT[HDIM*G4];       // Whh^T [k][j]
__device__ float g_h[NPATH*HDIM];
__device__ float g_logits[NPATH];
__device__ float g_e[NPATH];
__device__ unsigned g_gmax[GRP];
__device__ float g_gsum[GRP];
__device__ float g_cnt[GRP];
__device__ float g_wsum[GRP*HDIM];
__device__ int g_lcnt[40];
__device__ int g_lstart[40];
__device__ int g_perm[NPATH];
__device__ int g_nrows;
__device__ int g_rows[RTOT];

__device__ __forceinline__ float sigm(float x) { return 1.0f / (1.0f + expf(-x)); }

__device__ __forceinline__ unsigned enc_f(float f) {
    unsigned u = __float_as_uint(f);
    return (u & 0x80000000u) ? ~u : (u | 0x80000000u);
}
__device__ __forceinline__ float dec_f(unsigned k) {
    return (k & 0x80000000u) ? __uint_as_float(k ^ 0x80000000u) : __uint_as_float(~k);
}

// ---------------- packed f32x2 helpers ----------------
__device__ __forceinline__ ull fma2(ull a, ull b, ull c) {
    ull d;
    asm("fma.rn.f32x2 %0, %1, %2, %3;" : "=l"(d) : "l"(a), "l"(b), "l"(c));
    return d;
}
__device__ __forceinline__ ull pack2(float x, float y) {
    ull d;
    asm("mov.b64 %0, {%1, %2};" : "=l"(d) : "f"(x), "f"(y));
    return d;
}
__device__ __forceinline__ float2 unpack2(ull v) {
    float2 r;
    asm("mov.b64 {%0, %1}, %2;" : "=f"(r.x), "=f"(r.y) : "l"(v));
    return r;
}

// ---------------- sort kernels (counting sort by length, descending) ----------------
__global__ void k_hist(const int* __restrict__ lens) {
    int n = blockIdx.x * 256 + threadIdx.x;
    if (n < NPATH) atomicAdd(&g_lcnt[lens[n]], 1);
}
__global__ void k_scan() {
    if (threadIdx.x == 0 && blockIdx.x == 0) {
        int run = 0;
        for (int l = LMAX; l >= 1; l--) { g_lstart[l] = run; run += g_lcnt[l]; }
    }
}
__global__ void k_scatter(const int* __restrict__ lens) {
    int n = blockIdx.x * 256 + threadIdx.x;
    if (n < NPATH) {
        int pos = atomicAdd(&g_lstart[lens[n]], 1);
        g_perm[pos] = n;
    }
}
// packed valid-row list: g_rows[i] = path*32 + t for every valid (path,t)
__global__ void k_rowlist(const int* __restrict__ lens) {
    int n = blockIdx.x * 256 + threadIdx.x;
    if (n < NPATH) {
        int l = lens[n];
        int pos = atomicAdd(&g_nrows, l);
        int base = n * LMAX;
        for (int t = 0; t < l; t++) g_rows[pos + t] = base + t;
    }
}

// ---------------- kernel 0: transpose Whh once ----------------
__global__ void __launch_bounds__(256) k_tw(const float* __restrict__ Whh) {
    int idx = blockIdx.x * 256 + threadIdx.x;   // 65536 total
    int j = idx >> 7, k = idx & 127;
    g_WhhT[k * G4 + j] = Whh[j * HDIM + k];
}

// ---------------- kernel 1: fused projection+LN+tanh + input-gate GEMM ----------------
// block = 64 PACKED valid rows. No divergence, no wasted FMA.
__global__ void __launch_bounds__(256, 3) k_fp(const float* __restrict__ inp,
                                               const float* __restrict__ W_in,
                                               const float* __restrict__ gamma,
                                               const float* __restrict__ beta,
                                               const float* __restrict__ Wih,
                                               const float* __restrict__ bih,
                                               const float* __restrict__ bhh) {
    extern __shared__ float sm[];
    float* Xs = sm;                  // 64*132 = 8448
    float* Ad = sm + 8448;           // 32 kk * 132 (dup pairs) = 4224
    float* Bs = Ad + 4224;           // 32*132 = 4224  -> total 16896 fl = 67584 B
    __shared__ int srow[64];

    const int tid = threadIdx.x;
    const int tx = tid & 15, ty = tid >> 4;
    const int base = blockIdx.x * 64;
    const int nrows = g_nrows;
    if (base >= nrows) return;

    if (tid < 64) srow[tid] = (base + tid < nrows) ? g_rows[base + tid] : g_rows[base];
    __syncthreads();

    // ---- phase 1: x = tanh(LN(inp @ W_in^T)) ----
    ull acc[4][4];
#pragma unroll
    for (int i = 0; i < 4; i++)
#pragma unroll
        for (int j = 0; j < 4; j++) acc[i][j] = 0ull;

    for (int kt = 0; kt < 8; kt++) {
        __syncthreads();
        const int kb = kt * 32;
#pragma unroll
        for (int s = 0; s < 8; s++) {
            int idx = tid + s * 256;
            int kk = idx & 31, r = idx >> 5;
            float v = inp[(size_t)srow[r] * DIN + kb + kk];
            *(float2*)&Ad[kk * 132 + 2 * r] = make_float2(v, v);
        }
#pragma unroll
        for (int s = 0; s < 16; s++) {
            int idx = tid + s * 256;
            int kk = idx & 31, e = idx >> 5;
            Bs[kk * 132 + e] = W_in[e * DIN + kb + kk];
        }
        __syncthreads();
#pragma unroll 8
        for (int kk = 0; kk < 32; kk++) {
            ulonglong2 a01 = *(const ulonglong2*)&Ad[kk * 132 + 8 * ty];
            ulonglong2 a23 = *(const ulonglong2*)&Ad[kk * 132 + 8 * ty + 4];
            ull A2[4] = {a01.x, a01.y, a23.x, a23.y};
            ulonglong2 b01 = *(const ulonglong2*)&Bs[kk * 132 + tx * 8];
            ulonglong2 b23 = *(const ulonglong2*)&Bs[kk * 132 + tx * 8 + 4];
#pragma unroll
            for (int i = 0; i < 4; i++) {
                acc[i][0] = fma2(A2[i], b01.x, acc[i][0]);
                acc[i][1] = fma2(A2[i], b01.y, acc[i][1]);
                acc[i][2] = fma2(A2[i], b23.x, acc[i][2]);
                acc[i][3] = fma2(A2[i], b23.y, acc[i][3]);
            }
        }
    }

    {
        float gam[8], bet[8];
#pragma unroll
        for (int j = 0; j < 8; j++) { gam[j] = gamma[tx * 8 + j]; bet[j] = beta[tx * 8 + j]; }
#pragma unroll
        for (int i = 0; i < 4; i++) {
            float v[8];
#pragma unroll
            for (int p = 0; p < 4; p++) {
                float2 u = unpack2(acc[i][p]);
                v[2 * p] = u.x; v[2 * p + 1] = u.y;
            }
            float s = 0.0f, q = 0.0f;
#pragma unroll
            for (int j = 0; j < 8; j++) { s += v[j]; q += v[j] * v[j]; }
#pragma unroll
            for (int m = 8; m >= 1; m >>= 1) {
                s += __shfl_xor_sync(0xffffffffu, s, m);
                q += __shfl_xor_sync(0xffffffffu, q, m);
            }
            float mu = s * (1.0f / 128.0f);
            float var = q * (1.0f / 128.0f) - mu * mu;
            float rs = rsqrtf(var + LN_EPS);
            int r = ty * 4 + i;
            float o[8];
#pragma unroll
            for (int j = 0; j < 8; j++) o[j] = tanhf((v[j] - mu) * rs * gam[j] + bet[j]);
            float4* dst = (float4*)&Xs[r * 132 + tx * 8];
            dst[0] = make_float4(o[0], o[1], o[2], o[3]);
            dst[1] = make_float4(o[4], o[5], o[6], o[7]);
        }
    }

    // ---- phase 2: gi = Xs @ Wih^T + b ----
    for (int j0t = 0; j0t < 4; j0t++) {
        const int j0 = j0t * 128;
        ull acc2[4][4];
#pragma unroll
        for (int i = 0; i < 4; i++)
#pragma unroll
            for (int j = 0; j < 4; j++) acc2[i][j] = 0ull;

        for (int kt = 0; kt < 4; kt++) {
            __syncthreads();
            const int kb = kt * 32;
#pragma unroll
            for (int s = 0; s < 16; s++) {
                int idx = tid + s * 256;
                int kk = idx & 31, j = idx >> 5;
                Bs[kk * 132 + j] = Wih[(j0 + j) * HDIM + kb + kk];
            }
            __syncthreads();
#pragma unroll 8
            for (int kk = 0; kk < 32; kk++) {
                ull a2[4];
#pragma unroll
                for (int i = 0; i < 4; i++) {
                    float a = Xs[(ty * 4 + i) * 132 + kb + kk];
                    a2[i] = pack2(a, a);
                }
                ulonglong2 b01 = *(const ulonglong2*)&Bs[kk * 132 + tx * 8];
                ulonglong2 b23 = *(const ulonglong2*)&Bs[kk * 132 + tx * 8 + 4];
#pragma unroll
                for (int i = 0; i < 4; i++) {
                    acc2[i][0] = fma2(a2[i], b01.x, acc2[i][0]);
                    acc2[i][1] = fma2(a2[i], b01.y, acc2[i][1]);
                    acc2[i][2] = fma2(a2[i], b23.x, acc2[i][2]);
                    acc2[i][3] = fma2(a2[i], b23.y, acc2[i][3]);
                }
            }
        }
        {
            float bs[8];
#pragma unroll
            for (int j = 0; j < 8; j++) {
                int jj = j0 + tx * 8 + j;
                bs[j] = bih[jj] + bhh[jj];
            }
#pragma unroll
            for (int i = 0; i < 4; i++) {
                int r = ty * 4 + i;
                if (base + r < nrows) {
                    float v[8];
#pragma unroll
                    for (int pp = 0; pp < 4; pp++) {
                        float2 u = unpack2(acc2[i][pp]);
                        v[2 * pp] = u.x; v[2 * pp + 1] = u.y;
                    }
                    size_t gbase = (size_t)srow[r] * G4 + j0 + tx * 8;
                    float4* dst = (float4*)&g_gi[gbase];
                    dst[0] = make_float4(v[0] + bs[0], v[1] + bs[1], v[2] + bs[2], v[3] + bs[3]);
                    dst[1] = make_float4(v[4] + bs[4], v[5] + bs[5], v[6] + bs[6], v[7] + bs[7]);
                }
            }
        }
    }
}

// ---------------- kernel 2: LSTM recurrence (sorted, balanced, dup-h) ----------------
__global__ void __launch_bounds__(256, 2) k_lstm(const int* __restrict__ lens) {
    extern __shared__ float sm[];
    float* hs = sm;                 // 128 * 68 = 8704 floats (dup-transposed)
    float* Bs = sm + 8704;          // 32 * 520 = 16640 -> total 25344 fl = 101376 B
    __shared__ int ln_s[32];
    __shared__ int sp[32];
    __shared__ int maxlen_s;

    const int tid = threadIdx.x;
    const int tx = tid & 31, ty = tid >> 5;
    const int bid = blockIdx.x;
    const int gidx = (bid < 148) ? bid : (403 - bid);
    const int n0 = gidx * 32;

#pragma unroll
    for (int s = 0; s < 34; s++) {
        int idx = tid + s * 256;
        if (idx < 8704) hs[idx] = 0.0f;
    }
    if (tid < 32) {
        int pid = g_perm[n0 + tid];
        sp[tid] = pid;
        int l = lens[pid];
        ln_s[tid] = l;
#pragma unroll
        for (int m = 16; m >= 1; m >>= 1) l = max(l, __shfl_xor_sync(0xffffffffu, l, m));
        if (tid == 0) maxlen_s = l;
    }
    __syncthreads();

    int myln[4];
    int pid4[4];
    int mymax = 0;
#pragma unroll
    for (int i = 0; i < 4; i++) {
        myln[i] = ln_s[4 * ty + i];
        pid4[i] = sp[4 * ty + i];
        mymax = max(mymax, myln[i]);
    }
    const int blkmax = maxlen_s;

    float c[4][4];
#pragma unroll
    for (int i = 0; i < 4; i++)
#pragma unroll
        for (int j = 0; j < 4; j++) c[i][j] = 0.0f;

    for (int t = 0; t < blkmax; t++) {
        ull acc[4][4][2];
#pragma unroll
        for (int i = 0; i < 4; i++)
#pragma unroll
            for (int q = 0; q < 4; q++) { acc[i][q][0] = 0ull; acc[i][q][1] = 0ull; }

        const bool active = (t < mymax);

        for (int kt = 0; kt < 4; kt++) {
            __syncthreads();
#pragma unroll
            for (int s = 0; s < 16; s++) {
                int f4 = tid + s * 256;
                int kk = f4 >> 7;
                int col = (f4 & 127) * 4;
                *(float4*)&Bs[kk * 520 + col] =
                    *(const float4*)&g_WhhT[(kt * 32 + kk) * G4 + col];
            }
            __syncthreads();
            if (active) {
                const int kb = kt * 32;
#pragma unroll 8
                for (int kk = 0; kk < 32; kk++) {
                    ulonglong2 a01 = *(const ulonglong2*)&hs[(kb + kk) * 68 + 8 * ty];
                    ulonglong2 a23 = *(const ulonglong2*)&hs[(kb + kk) * 68 + 8 * ty + 4];
                    ull A2[4] = {a01.x, a01.y, a23.x, a23.y};
#pragma unroll
                    for (int q = 0; q < 4; q++) {
                        ulonglong2 b = *(const ulonglong2*)&Bs[kk * 520 + q * 128 + tx * 4];
#pragma unroll
                        for (int i = 0; i < 4; i++) {
                            acc[i][q][0] = fma2(A2[i], b.x, acc[i][q][0]);
                            acc[i][q][1] = fma2(A2[i], b.y, acc[i][q][1]);
                        }
                    }
                }
            }
        }

        if (active) {
#pragma unroll
            for (int i = 0; i < 4; i++) {
                if (t < myln[i]) {
                    int n = 4 * ty + i;
                    size_t base = ((size_t)pid4[i] * LMAX + t) * G4 + tx * 4;
                    float4 gi = *(const float4*)&g_gi[base];
                    float4 gf = *(const float4*)&g_gi[base + 128];
                    float4 gg = *(const float4*)&g_gi[base + 256];
                    float4 go = *(const float4*)&g_gi[base + 384];
                    float2 i0 = unpack2(acc[i][0][0]), i1 = unpack2(acc[i][0][1]);
                    float2 f0 = unpack2(acc[i][1][0]), f1 = unpack2(acc[i][1][1]);
                    float2 g0 = unpack2(acc[i][2][0]), g1 = unpack2(acc[i][2][1]);
                    float2 o0 = unpack2(acc[i][3][0]), o1 = unpack2(acc[i][3][1]);
                    float xi[4] = {gi.x + i0.x, gi.y + i0.y, gi.z + i1.x, gi.w + i1.y};
                    float xf[4] = {gf.x + f0.x, gf.y + f0.y, gf.z + f1.x, gf.w + f1.y};
                    float xg[4] = {gg.x + g0.x, gg.y + g0.y, gg.z + g1.x, gg.w + g1.y};
                    float xo[4] = {go.x + o0.x, go.y + o0.y, go.z + o1.x, go.w + o1.y};
#pragma unroll
                    for (int j = 0; j < 4; j++) {
                        float cn = sigm(xf[j]) * c[i][j] + sigm(xi[j]) * tanhf(xg[j]);
                        c[i][j] = cn;
                        float h = sigm(xo[j]) * tanhf(cn);
                        *(float2*)&hs[(tx * 4 + j) * 68 + 2 * n] = make_float2(h, h);
                    }
                }
            }
        }
        __syncthreads();
    }

#pragma unroll
    for (int s = 0; s < 16; s++) {
        int idx = tid + s * 256;
        int n = idx >> 7, k = idx & 127;
        g_h[(size_t)sp[n] * HDIM + k] = hs[k * 68 + 2 * n];
    }
}

// ---------------- kernel 3a: init accumulators (+ counters) ----------------
__global__ void k_init() {
    int i = blockIdx.x * blockDim.x + threadIdx.x;
    if (i < GRP * HDIM) g_wsum[i] = 0.0f;
    if (i < GRP) {
        g_gsum[i] = 0.0f;
        g_cnt[i] = 0.0f;
        g_gmax[i] = 0u;
    }
    if (i < 40) g_lcnt[i] = 0;
    if (i == 0) g_nrows = 0;
}

// ---------------- kernel 3b: attention logits + segment max ----------------
__global__ void __launch_bounds__(256) k_logits(const float* __restrict__ ap,
                                                const int* __restrict__ seg) {
    int w = threadIdx.x >> 5, lane = threadIdx.x & 31;
    int n = blockIdx.x * 8 + w;
    float s = 0.0f;
#pragma unroll
    for (int q = 0; q < 4; q++) s += g_h[n * HDIM + lane + 32 * q] * ap[lane + 32 * q];
#pragma unroll
    for (int m = 16; m >= 1; m >>= 1) s += __shfl_xor_sync(0xffffffffu, s, m);
    if (lane == 0) {
        g_logits[n] = s;
        atomicMax(&g_gmax[seg[n]], enc_f(s));
    }
}

// ---------------- kernel 3c: exp + segment sum + count ----------------
__global__ void __launch_bounds__(256) k_expsum(const int* __restrict__ seg) {
    int n = blockIdx.x * 256 + threadIdx.x;
    int g = seg[n];
    float e = expf(g_logits[n] - dec_f(g_gmax[g]));
    g_e[n] = e;
    atomicAdd(&g_gsum[g], e);
    atomicAdd(&g_cnt[g], 1.0f);
}

// ---------------- kernel 3d: weighted hidden sum per group ----------------
__global__ void __launch_bounds__(256) k_wsum(const int* __restrict__ seg) {
    int w = threadIdx.x >> 5, lane = threadIdx.x & 31;
    int n = blockIdx.x * 8 + w;
    float e = g_e[n];
    int g = seg[n];
#pragma unroll
    for (int q = 0; q < 4; q++)
        atomicAdd(&g_wsum[g * HDIM + lane + 32 * q], e * g_h[n * HDIM + lane + 32 * q]);
}

// ---------------- kernel 4: head ----------------
__global__ void __launch_bounds__(256) k_head(const float* __restrict__ W_out,
                                              const float* __restrict__ W_cls,
                                              const float* __restrict__ ap,
                                              float* __restrict__ out,
                                              int out_size) {
    __shared__ float cs[16 * 128];
    __shared__ float cvs[16 * 128];
    const int tid = threadIdx.x;
    const int g0 = blockIdx.x * 16;
    const bool full = (out_size >= 2048 + GRP * HDIM + HDIM);

#pragma unroll
    for (int s = 0; s < 8; s++) {
        int idx = tid + s * 256;
        int gg = idx >> 7, k = idx & 127;
        int gi = g0 + gg;
        cs[gg * 128 + k] = g_wsum[gi * HDIM + k] / (g_gsum[gi] * g_cnt[gi]);
    }
    __syncthreads();

    int row = tid >> 4;
    int c0 = (tid & 15) * 8;
    float acc[8];
#pragma unroll
    for (int j = 0; j < 8; j++) acc[j] = 0.0f;
    for (int k = 0; k < 128; k++) {
        float a = cs[row * 128 + k];
#pragma unroll
        for (int j = 0; j < 8; j++) acc[j] += a * W_out[(c0 + j) * 128 + k];
    }
#pragma unroll
    for (int j = 0; j < 8; j++) {
        cvs[row * 128 + c0 + j] = acc[j];
        if (full) out[2048 + (g0 + row) * 128 + c0 + j] = acc[j];
    }
    __syncthreads();

    if (tid < 32) {
        int r = tid >> 1, c = tid & 1;
        float s = 0.0f;
        for (int k = 0; k < 128; k++) s += cvs[r * 128 + k] * W_cls[c * 128 + k];
        out[(g0 + r) * 2 + c] = s;
    }
    if (full && blockIdx.x == 0 && tid < 128) out[2048 + GRP * HDIM + tid] = ap[tid];
}

// ---------------- launch ----------------
extern "C" void kernel_launch(void* const* d_in, const int* in_sizes, int n_in,
                              void* d_out, int out_size) {
    const float* inputs = (const float*)d_in[0];
    const int* lens     = (const int*)d_in[1];
    const int* seg      = (const int*)d_in[2];
    const float* W_in   = (const float*)d_in[3];
    const float* gamma  = (const float*)d_in[4];
    const float* beta   = (const float*)d_in[5];
    const float* Wih    = (const float*)d_in[6];
    const float* Whh    = (const float*)d_in[7];
    const float* bih    = (const float*)d_in[8];
    const float* bhh    = (const float*)d_in[9];
    const float* ap     = (const float*)d_in[10];
    const float* W_out  = (const float*)d_in[11];
    const float* W_cls  = (const float*)d_in[12];
    float* out = (float*)d_out;

    const int fp_smem   = 16896 * 4;   // 67584 B
    const int lstm_smem = 25344 * 4;   // 101376 B
    cudaFuncSetAttribute(k_fp, cudaFuncAttributeMaxDynamicSharedMemorySize, fp_smem);
    cudaFuncSetAttribute(k_lstm, cudaFuncAttributeMaxDynamicSharedMemorySize, lstm_smem);

    k_init<<<(GRP * HDIM + 255) / 256, 256>>>();
    k_hist<<<NPATH / 256, 256>>>(lens);
    k_scan<<<1, 32>>>();
    k_scatter<<<NPATH / 256, 256>>>(lens);
    k_rowlist<<<NPATH / 256, 256>>>(lens);
    k_tw<<<256, 256>>>(Whh);
    k_fp<<<RTOT / 64, 256, fp_smem>>>(inputs, W_in, gamma, beta, Wih, bih, bhh);
    k_lstm<<<NPATH / 32, 256, lstm_smem>>>(lens);
    k_logits<<<NPATH / 8, 256>>>(ap, seg);
    k_expsum<<<NPATH / 256, 256>>>(seg);
    k_wsum<<<NPATH / 8, 256>>>(seg);
    k_head<<<GRP / 16, 256>>>(W_out, W_cls, ap, out, out_size);
}